// round 15
// baseline (speedup 1.0000x reference)
#include <cuda_runtime.h>
#include <cuda_fp16.h>
#include <math.h>
#include <stdint.h>

#define NN      4096
#define IN_DIM  128
#define HEADS   4
#define OUT_DIM 64
#define HD      256
#define MT      128
#define KSPL    4
#define JC      128
#define NCH     (NN / KSPL / JC)    // 8 chunks per block
#define PCOLS   264

// ---- persistent scratch ----
__device__ uint4  g_hb[NN * 32];        // h fp16 row-major (hmean fallback)
__device__ __half g_hT[HD * NN];        // h fp16 transposed [dim][j]
__device__ float  g_si[NN * HEADS];
__device__ float  g_sj[NN * HEADS];
__device__ float  g_mx[HEADS];
__device__ float4 g_efs[HEADS * NN];    // per (head, j): (sj, E, F, 0)
__device__ float  g_hmean[HD];
__device__ float  g_part[(size_t)KSPL * NN * PCOLS];

// --------------------------------------------------------------------------
// Kernel 1: h = x @ W (fp16 row-major + transposed) + fused scores.
// --------------------------------------------------------------------------
__global__ __launch_bounds__(256) void gemm_h_kernel(const float* __restrict__ x,
                                                     const float* __restrict__ W,
                                                     const float* __restrict__ a_src,
                                                     const float* __restrict__ a_dst) {
    __shared__ float xs[16][IN_DIM];
    __shared__ float s_si[16][HEADS];
    __shared__ float s_sj[16][HEADS];
    const int t = threadIdx.x;
    const int row0 = blockIdx.x * 16;

    for (int idx = t; idx < 16 * IN_DIM; idx += 256)
        xs[idx >> 7][idx & 127] = x[row0 * IN_DIM + idx];
    if (t < 64) { s_si[t >> 2][t & 3] = 0.f; s_sj[t >> 2][t & 3] = 0.f; }
    __syncthreads();

    const int slot = t & 63;
    const int grp  = t >> 6;
    float4 acc[4];
#pragma unroll
    for (int r = 0; r < 4; r++) acc[r] = make_float4(0.f, 0.f, 0.f, 0.f);

    const float4* W4 = (const float4*)W;
#pragma unroll
    for (int kc = 0; kc < IN_DIM; kc += 8) {
        float4 wv[8];
#pragma unroll
        for (int u = 0; u < 8; u++) wv[u] = W4[(kc + u) * 64 + slot];
#pragma unroll
        for (int u = 0; u < 8; u++) {
#pragma unroll
            for (int r = 0; r < 4; r++) {
                float xv = xs[grp * 4 + r][kc + u];
                acc[r].x = fmaf(xv, wv[u].x, acc[r].x);
                acc[r].y = fmaf(xv, wv[u].y, acc[r].y);
                acc[r].z = fmaf(xv, wv[u].z, acc[r].z);
                acc[r].w = fmaf(xv, wv[u].w, acc[r].w);
            }
        }
    }
    __half2* HB = (__half2*)g_hb;
#pragma unroll
    for (int r = 0; r < 4; r++) {
        int row = row0 + grp * 4 + r;
        HB[(size_t)row * 128 + slot * 2]     = __floats2half2_rn(acc[r].x, acc[r].y);
        HB[(size_t)row * 128 + slot * 2 + 1] = __floats2half2_rn(acc[r].z, acc[r].w);
    }
    {
        int rbase = row0 + grp * 4;
#pragma unroll
        for (int dd = 0; dd < 4; dd++) {
            float v0 = dd == 0 ? acc[0].x : dd == 1 ? acc[0].y : dd == 2 ? acc[0].z : acc[0].w;
            float v1 = dd == 0 ? acc[1].x : dd == 1 ? acc[1].y : dd == 2 ? acc[1].z : acc[1].w;
            float v2 = dd == 0 ? acc[2].x : dd == 1 ? acc[2].y : dd == 2 ? acc[2].z : acc[2].w;
            float v3 = dd == 0 ? acc[3].x : dd == 1 ? acc[3].y : dd == 2 ? acc[3].z : acc[3].w;
            __half2 lo = __floats2half2_rn(v0, v1);
            __half2 hi = __floats2half2_rn(v2, v3);
            uint2 u = make_uint2(*(uint32_t*)&lo, *(uint32_t*)&hi);
            int dim = slot * 4 + dd;
            *(uint2*)(g_hT + (size_t)dim * NN + rbase) = u;
        }
    }
    const int d0 = (slot * 4) & 63;
    const int hh = slot >> 4;
    float as0 = a_src[d0], as1 = a_src[d0 + 1], as2 = a_src[d0 + 2], as3 = a_src[d0 + 3];
    float ad0 = a_dst[d0], ad1 = a_dst[d0 + 1], ad2 = a_dst[d0 + 2], ad3 = a_dst[d0 + 3];
#pragma unroll
    for (int r = 0; r < 4; r++) {
        float psi = acc[r].x * as0 + acc[r].y * as1 + acc[r].z * as2 + acc[r].w * as3;
        float psj = acc[r].x * ad0 + acc[r].y * ad1 + acc[r].z * ad2 + acc[r].w * ad3;
        atomicAdd(&s_si[grp * 4 + r][hh], psi);
        atomicAdd(&s_sj[grp * 4 + r][hh], psj);
    }
    __syncthreads();
    if (t < 64) {
        g_si[(row0 + (t >> 2)) * HEADS + (t & 3)] = s_si[t >> 2][t & 3];
        g_sj[(row0 + (t >> 2)) * HEADS + (t & 3)] = s_sj[t >> 2][t & 3];
    }
}

// --------------------------------------------------------------------------
// Kernel 2: g_mx[h] = max_n sj.
// --------------------------------------------------------------------------
__global__ __launch_bounds__(256) void max_sj_kernel() {
    __shared__ float red[HEADS][8];
    const int t = threadIdx.x, lane = t & 31, wid = t >> 5;
    float mx[HEADS];
#pragma unroll
    for (int h = 0; h < HEADS; h++) mx[h] = -INFINITY;
    const float4* s4 = (const float4*)g_sj;
    for (int i = t; i < NN; i += 256) {
        float4 v = s4[i];
        mx[0] = fmaxf(mx[0], v.x); mx[1] = fmaxf(mx[1], v.y);
        mx[2] = fmaxf(mx[2], v.z); mx[3] = fmaxf(mx[3], v.w);
    }
#pragma unroll
    for (int h = 0; h < HEADS; h++)
#pragma unroll
        for (int d = 16; d; d >>= 1)
            mx[h] = fmaxf(mx[h], __shfl_xor_sync(0xffffffffu, mx[h], d));
    if (lane == 0)
#pragma unroll
        for (int h = 0; h < HEADS; h++) red[h][wid] = mx[h];
    __syncthreads();
    if (t < HEADS) {
        float m = red[t][0];
#pragma unroll
        for (int w = 1; w < 8; w++) m = fmaxf(m, red[t][w]);
        g_mx[t] = m;
    }
}

// --------------------------------------------------------------------------
// Kernel 3: factor tables g_efs[h][j] = (sj, E, F, 0).
// --------------------------------------------------------------------------
__global__ __launch_bounds__(256) void ef_kernel() {
    int j = blockIdx.x * 256 + threadIdx.x;
    if (j >= NN) return;
    float4 sj = ((const float4*)g_sj)[j];
    float s[4] = {sj.x, sj.y, sj.z, sj.w};
#pragma unroll
    for (int h = 0; h < HEADS; h++) {
        float d = s[h] - g_mx[h];
        g_efs[h * NN + j] = make_float4(s[h], __expf(d), __expf(0.2f * d), 0.f);
    }
}

// --------------------------------------------------------------------------
// Kernel 4: column means of h (degree-0 fallback).
// --------------------------------------------------------------------------
__global__ __launch_bounds__(256) void hmean_kernel() {
    __shared__ float red[256][8];
    const int c = blockIdx.x, t = threadIdx.x;
    float a[8] = {0.f, 0.f, 0.f, 0.f, 0.f, 0.f, 0.f, 0.f};
    for (int j = t; j < NN; j += 256) {
        uint4 v = g_hb[(size_t)j * 32 + c];
        float2 f0 = __half22float2(*(__half2*)&v.x);
        float2 f1 = __half22float2(*(__half2*)&v.y);
        float2 f2 = __half22float2(*(__half2*)&v.z);
        float2 f3 = __half22float2(*(__half2*)&v.w);
        a[0] += f0.x; a[1] += f0.y; a[2] += f1.x; a[3] += f1.y;
        a[4] += f2.x; a[5] += f2.y; a[6] += f3.x; a[7] += f3.y;
    }
#pragma unroll
    for (int d = 0; d < 8; d++) red[t][d] = a[d];
    __syncthreads();
    if (t < 8) {
        float s = 0.f;
        for (int w = 0; w < 256; w++) s += red[w][t];
        g_hmean[c * 8 + t] = s * (1.0f / NN);
    }
}

// --------------------------------------------------------------------------
// Kernel 5: dense flash-GAT on mma.sync (HMMA m16n8k16).
// grid (32, 4), 256 threads (8 warps). warp = (i_half, head).
// --------------------------------------------------------------------------
#define HTP   136                     // padded stride (halves): conflict-free
#define SMO_SIAB 0                    // [4][128] float4 = 8192
#define SMO_EFS  8192                 // [4][128] float4 = 8192
#define SMO_MASK 16384                // [128][HTP] half  = 34816
#define SMO_HT   51200                // [256][HTP] half  = 69632
#define SM_TOT   120832

__device__ __forceinline__ float pcalc(const float4& sab, const float4& efs) {
    float s = sab.x + efs.x;
    return (s >= 0.f) ? sab.y * efs.y : sab.z * efs.z;
}

__global__ __launch_bounds__(256, 1) void attn_kernel(const int* __restrict__ mask) {
    extern __shared__ __align__(16) char sm[];
    float4* siab   = (float4*)(sm + SMO_SIAB);   // [h*128 + i]
    float4* efs    = (float4*)(sm + SMO_EFS);    // [h*128 + j]
    __half* mask_s = (__half*)(sm + SMO_MASK);   // [i][HTP]
    __half* ht_s   = (__half*)(sm + SMO_HT);     // [dim][HTP]

    const int t    = threadIdx.x;
    const int lane = t & 31;
    const int warp = t >> 5;
    const int head  = warp & 3;
    const int ihalf = warp >> 2;        // 0/1 -> 64 rows
    const int g     = lane >> 2;        // fragment group row
    const int qc    = lane & 3;         // fragment col group
    const int i0 = blockIdx.x * MT;
    const int ks = blockIdx.y;

    // stage SIAB once
    for (int idx = t; idx < 512; idx += 256) {
        int h = idx >> 7, i = idx & 127;
        float si = g_si[(size_t)(i0 + i) * 4 + h];
        float v = si + g_mx[h];
        float mm = fmaxf(v, 0.2f * v);
        siab[idx] = make_float4(si, __expf(v - mm), __expf(0.2f * v - mm), 0.f);
    }

    float acc[4][8][4];
#pragma unroll
    for (int a = 0; a < 4; a++)
#pragma unroll
        for (int b = 0; b < 8; b++)
#pragma unroll
            for (int d = 0; d < 4; d++) acc[a][b][d] = 0.f;
    float psum[4][2];
#pragma unroll
    for (int a = 0; a < 4; a++) { psum[a][0] = 0.f; psum[a][1] = 0.f; }

    const int4* m4 = (const int4*)mask;

    for (int c = 0; c < NCH; c++) {
        const int j0 = ks * (NN / KSPL) + c * JC;
        __syncthreads();
        // ---- stage hT tile [256 dims][128 j]  (16 uint4 per dim row) ----
        for (int idx = t; idx < 4096; idx += 256) {
            int r = idx >> 4, q = idx & 15;
            uint4 v = *(const uint4*)(g_hT + (size_t)r * NN + j0 + q * 8);
            *(uint4*)(ht_s + r * HTP + q * 8) = v;
        }
        // ---- stage mask -> f16 0/1 ----
        for (int idx = t; idx < 4096; idx += 256) {
            int i = idx >> 5, w = idx & 31;
            int4 v = m4[(size_t)(i0 + i) * (NN / 4) + (j0 >> 2) + w];
            uint32_t lo = (v.x ? 0x3C00u : 0u) | (v.y ? 0x3C000000u : 0u);
            uint32_t hi = (v.z ? 0x3C00u : 0u) | (v.w ? 0x3C000000u : 0u);
            *(uint2*)(mask_s + i * HTP + w * 4) = make_uint2(lo, hi);
        }
        // ---- stage efs ----
        for (int idx = t; idx < 512; idx += 256) {
            int h = idx >> 7, j = idx & 127;
            efs[h * 128 + j] = g_efs[(size_t)h * NN + j0 + j];
        }
        __syncthreads();

#pragma unroll 1
        for (int k2 = 0; k2 < JC / 16; k2++) {
            const int jk = k2 * 16;
            // ---- load B fragments (8 n-tiles) ----
            uint32_t b0[8], b1[8];
#pragma unroll
            for (int nt = 0; nt < 8; nt++) {
                int dim = head * 64 + nt * 8 + g;
                const __half* bp = ht_s + dim * HTP + jk + qc * 2;
                b0[nt] = *(const uint32_t*)bp;
                b1[nt] = *(const uint32_t*)(bp + 8);
            }
#pragma unroll
            for (int isub = 0; isub < 4; isub++) {
                const int r0 = ihalf * 64 + isub * 16 + g;
                const int r1 = r0 + 8;
                float4 s0 = siab[head * 128 + r0];
                float4 s1 = siab[head * 128 + r1];
                const int cb = jk + qc * 2;
                float4 e0 = efs[head * 128 + cb];
                float4 e1 = efs[head * 128 + cb + 1];
                float4 e8 = efs[head * 128 + cb + 8];
                float4 e9 = efs[head * 128 + cb + 9];
                float2 m0a = __half22float2(*(__half2*)(mask_s + r0 * HTP + cb));
                float2 m0b = __half22float2(*(__half2*)(mask_s + r0 * HTP + cb + 8));
                float2 m1a = __half22float2(*(__half2*)(mask_s + r1 * HTP + cb));
                float2 m1b = __half22float2(*(__half2*)(mask_s + r1 * HTP + cb + 8));
                float p00 = pcalc(s0, e0) * m0a.x, p01 = pcalc(s0, e1) * m0a.y;
                float p08 = pcalc(s0, e8) * m0b.x, p09 = pcalc(s0, e9) * m0b.y;
                float p10 = pcalc(s1, e0) * m1a.x, p11 = pcalc(s1, e1) * m1a.y;
                float p18 = pcalc(s1, e8) * m1b.x, p19 = pcalc(s1, e9) * m1b.y;
                psum[isub][0] += p00 + p01 + p08 + p09;
                psum[isub][1] += p10 + p11 + p18 + p19;
                __half2 ha0 = __floats2half2_rn(p00, p01);
                __half2 ha1 = __floats2half2_rn(p10, p11);
                __half2 ha2 = __floats2half2_rn(p08, p09);
                __half2 ha3 = __floats2half2_rn(p18, p19);
                uint32_t a0 = *(uint32_t*)&ha0, a1 = *(uint32_t*)&ha1;
                uint32_t a2 = *(uint32_t*)&ha2, a3 = *(uint32_t*)&ha3;
#pragma unroll
                for (int nt = 0; nt < 8; nt++) {
                    asm volatile(
                        "mma.sync.aligned.m16n8k16.row.col.f32.f16.f16.f32 "
                        "{%0,%1,%2,%3}, {%4,%5,%6,%7}, {%8,%9}, {%0,%1,%2,%3};"
                        : "+f"(acc[isub][nt][0]), "+f"(acc[isub][nt][1]),
                          "+f"(acc[isub][nt][2]), "+f"(acc[isub][nt][3])
                        : "r"(a0), "r"(a1), "r"(a2), "r"(a3), "r"(b0[nt]), "r"(b1[nt]));
                }
            }
        }
    }

    // ---- epilogue: store partials + row sums ----
#pragma unroll
    for (int isub = 0; isub < 4; isub++) {
        int ir0 = i0 + ihalf * 64 + isub * 16 + g;
        int ir1 = ir0 + 8;
        float* d0 = g_part + ((size_t)ks * NN + ir0) * PCOLS;
        float* d1 = g_part + ((size_t)ks * NN + ir1) * PCOLS;
#pragma unroll
        for (int nt = 0; nt < 8; nt++) {
            int dd = head * 64 + nt * 8 + qc * 2;
            *(float2*)(d0 + dd) = make_float2(acc[isub][nt][0], acc[isub][nt][1]);
            *(float2*)(d1 + dd) = make_float2(acc[isub][nt][2], acc[isub][nt][3]);
        }
        float s0 = psum[isub][0], s1 = psum[isub][1];
        s0 += __shfl_xor_sync(0xffffffffu, s0, 1);
        s0 += __shfl_xor_sync(0xffffffffu, s0, 2);
        s1 += __shfl_xor_sync(0xffffffffu, s1, 1);
        s1 += __shfl_xor_sync(0xffffffffu, s1, 2);
        if (qc == 0) {
            d0[256 + head] = s0;
            d1[256 + head] = s1;
        }
    }
}

// --------------------------------------------------------------------------
// Kernel 6: split-K merge + normalize (+ degree-0 fallback).
// --------------------------------------------------------------------------
__global__ __launch_bounds__(256) void merge_kernel(float* __restrict__ out) {
    __shared__ float ss[HEADS];
    const int i = blockIdx.x, t = threadIdx.x;
    const float* p = g_part + (size_t)i * PCOLS;
    const size_t st = (size_t)NN * PCOLS;
    if (t < HEADS)
        ss[t] = p[256 + t] + p[st + 256 + t] + p[2 * st + 256 + t] + p[3 * st + 256 + t];
    __syncthreads();
    float v = p[t] + p[st + t] + p[2 * st + t] + p[3 * st + t];
    float s = ss[t >> 6];
    out[(size_t)i * HD + t] = (s > 0.f) ? v / s : g_hmean[t];
}

// --------------------------------------------------------------------------
extern "C" void kernel_launch(void* const* d_in, const int* in_sizes, int n_in,
                              void* d_out, int out_size) {
    const float* x     = (const float*)d_in[0];
    const int*   mask  = (const int*)d_in[1];
    const float* W     = (const float*)d_in[2];
    const float* a_src = (const float*)d_in[3];
    const float* a_dst = (const float*)d_in[4];
    float*       out   = (float*)d_out;

    cudaFuncSetAttribute(attn_kernel, cudaFuncAttributeMaxDynamicSharedMemorySize, SM_TOT);

    gemm_h_kernel<<<NN / 16, 256>>>(x, W, a_src, a_dst);
    max_sj_kernel<<<1, 256>>>();
    ef_kernel<<<NN / 256, 256>>>();
    hmean_kernel<<<32, 256>>>();
    attn_kernel<<<dim3(NN / MT, KSPL), 256, SM_TOT>>>(mask);
    merge_kernel<<<NN, 256>>>(out);
}

// round 16
// speedup vs baseline: 1.1426x; 1.1426x over previous
#include <cuda_runtime.h>
#include <cuda_fp16.h>
#include <math.h>
#include <stdint.h>

#define NN      4096
#define IN_DIM  128
#define HEADS   4
#define OUT_DIM 64
#define HD      256
#define MT      128
#define KSPL    4
#define JC      128
#define NCH     (NN / KSPL / JC)    // 8 chunks per block
#define PCOLS   264

// ---- persistent scratch ----
__device__ uint4  g_hb[NN * 32];        // h fp16 row-major
__device__ __half g_hT[HD * NN];        // h fp16 transposed [dim][j]
__device__ float  g_si[NN * HEADS];
__device__ float  g_sj[NN * HEADS];
__device__ float  g_mx[HEADS];
__device__ float4 g_efs[HEADS * NN];    // per (head, j): (sj, E, F, 0)
__device__ float  g_hmean[HD];
__device__ float  g_part[(size_t)KSPL * NN * PCOLS];

// --------------------------------------------------------------------------
// Kernel 1: h = x @ W (fp16 row-major + transposed) + fused scores.
// --------------------------------------------------------------------------
__global__ __launch_bounds__(256) void gemm_h_kernel(const float* __restrict__ x,
                                                     const float* __restrict__ W,
                                                     const float* __restrict__ a_src,
                                                     const float* __restrict__ a_dst) {
    __shared__ float xs[16][IN_DIM];
    __shared__ float s_si[16][HEADS];
    __shared__ float s_sj[16][HEADS];
    const int t = threadIdx.x;
    const int row0 = blockIdx.x * 16;

    for (int idx = t; idx < 16 * IN_DIM; idx += 256)
        xs[idx >> 7][idx & 127] = x[row0 * IN_DIM + idx];
    if (t < 64) { s_si[t >> 2][t & 3] = 0.f; s_sj[t >> 2][t & 3] = 0.f; }
    __syncthreads();

    const int slot = t & 63;
    const int grp  = t >> 6;
    float4 acc[4];
#pragma unroll
    for (int r = 0; r < 4; r++) acc[r] = make_float4(0.f, 0.f, 0.f, 0.f);

    const float4* W4 = (const float4*)W;
#pragma unroll
    for (int kc = 0; kc < IN_DIM; kc += 8) {
        float4 wv[8];
#pragma unroll
        for (int u = 0; u < 8; u++) wv[u] = W4[(kc + u) * 64 + slot];
#pragma unroll
        for (int u = 0; u < 8; u++) {
#pragma unroll
            for (int r = 0; r < 4; r++) {
                float xv = xs[grp * 4 + r][kc + u];
                acc[r].x = fmaf(xv, wv[u].x, acc[r].x);
                acc[r].y = fmaf(xv, wv[u].y, acc[r].y);
                acc[r].z = fmaf(xv, wv[u].z, acc[r].z);
                acc[r].w = fmaf(xv, wv[u].w, acc[r].w);
            }
        }
    }
    __half2* HB = (__half2*)g_hb;
#pragma unroll
    for (int r = 0; r < 4; r++) {
        int row = row0 + grp * 4 + r;
        HB[(size_t)row * 128 + slot * 2]     = __floats2half2_rn(acc[r].x, acc[r].y);
        HB[(size_t)row * 128 + slot * 2 + 1] = __floats2half2_rn(acc[r].z, acc[r].w);
    }
    {
        int rbase = row0 + grp * 4;
#pragma unroll
        for (int dd = 0; dd < 4; dd++) {
            float v0 = dd == 0 ? acc[0].x : dd == 1 ? acc[0].y : dd == 2 ? acc[0].z : acc[0].w;
            float v1 = dd == 0 ? acc[1].x : dd == 1 ? acc[1].y : dd == 2 ? acc[1].z : acc[1].w;
            float v2 = dd == 0 ? acc[2].x : dd == 1 ? acc[2].y : dd == 2 ? acc[2].z : acc[2].w;
            float v3 = dd == 0 ? acc[3].x : dd == 1 ? acc[3].y : dd == 2 ? acc[3].z : acc[3].w;
            __half2 lo = __floats2half2_rn(v0, v1);
            __half2 hi = __floats2half2_rn(v2, v3);
            uint2 u = make_uint2(*(uint32_t*)&lo, *(uint32_t*)&hi);
            int dim = slot * 4 + dd;
            *(uint2*)(g_hT + (size_t)dim * NN + rbase) = u;
        }
    }
    const int d0 = (slot * 4) & 63;
    const int hh = slot >> 4;
    float as0 = a_src[d0], as1 = a_src[d0 + 1], as2 = a_src[d0 + 2], as3 = a_src[d0 + 3];
    float ad0 = a_dst[d0], ad1 = a_dst[d0 + 1], ad2 = a_dst[d0 + 2], ad3 = a_dst[d0 + 3];
#pragma unroll
    for (int r = 0; r < 4; r++) {
        float psi = acc[r].x * as0 + acc[r].y * as1 + acc[r].z * as2 + acc[r].w * as3;
        float psj = acc[r].x * ad0 + acc[r].y * ad1 + acc[r].z * ad2 + acc[r].w * ad3;
        atomicAdd(&s_si[grp * 4 + r][hh], psi);
        atomicAdd(&s_sj[grp * 4 + r][hh], psj);
    }
    __syncthreads();
    if (t < 64) {
        g_si[(row0 + (t >> 2)) * HEADS + (t & 3)] = s_si[t >> 2][t & 3];
        g_sj[(row0 + (t >> 2)) * HEADS + (t & 3)] = s_sj[t >> 2][t & 3];
    }
}

// --------------------------------------------------------------------------
// Kernel 2: g_mx[h] = max_n sj.
// --------------------------------------------------------------------------
__global__ __launch_bounds__(256) void max_sj_kernel() {
    __shared__ float red[HEADS][8];
    const int t = threadIdx.x, lane = t & 31, wid = t >> 5;
    float mx[HEADS];
#pragma unroll
    for (int h = 0; h < HEADS; h++) mx[h] = -INFINITY;
    const float4* s4 = (const float4*)g_sj;
    for (int i = t; i < NN; i += 256) {
        float4 v = s4[i];
        mx[0] = fmaxf(mx[0], v.x); mx[1] = fmaxf(mx[1], v.y);
        mx[2] = fmaxf(mx[2], v.z); mx[3] = fmaxf(mx[3], v.w);
    }
#pragma unroll
    for (int h = 0; h < HEADS; h++)
#pragma unroll
        for (int d = 16; d; d >>= 1)
            mx[h] = fmaxf(mx[h], __shfl_xor_sync(0xffffffffu, mx[h], d));
    if (lane == 0)
#pragma unroll
        for (int h = 0; h < HEADS; h++) red[h][wid] = mx[h];
    __syncthreads();
    if (t < HEADS) {
        float m = red[t][0];
#pragma unroll
        for (int w = 1; w < 8; w++) m = fmaxf(m, red[t][w]);
        g_mx[t] = m;
    }
}

// --------------------------------------------------------------------------
// Kernel 3: factor tables g_efs[h][j] = (sj, E, F, 0).
// --------------------------------------------------------------------------
__global__ __launch_bounds__(256) void ef_kernel() {
    int j = blockIdx.x * 256 + threadIdx.x;
    if (j >= NN) return;
    float4 sj = ((const float4*)g_sj)[j];
    float s[4] = {sj.x, sj.y, sj.z, sj.w};
#pragma unroll
    for (int h = 0; h < HEADS; h++) {
        float d = s[h] - g_mx[h];
        g_efs[h * NN + j] = make_float4(s[h], __expf(d), __expf(0.2f * d), 0.f);
    }
}

// --------------------------------------------------------------------------
// Kernel 4: column means of h via g_hT rows (contiguous). Block = dim.
// --------------------------------------------------------------------------
__global__ __launch_bounds__(256) void hmean_kernel() {
    __shared__ float red[8];
    const int dim = blockIdx.x, t = threadIdx.x, lane = t & 31, wid = t >> 5;
    const __half2* p = (const __half2*)(g_hT + (size_t)dim * NN);
    float s = 0.f;
#pragma unroll 4
    for (int j = t; j < NN / 2; j += 256) {
        float2 f = __half22float2(p[j]);
        s += f.x + f.y;
    }
#pragma unroll
    for (int d = 16; d; d >>= 1) s += __shfl_xor_sync(0xffffffffu, s, d);
    if (lane == 0) red[wid] = s;
    __syncthreads();
    if (t == 0) {
        float tt = 0.f;
#pragma unroll
        for (int w = 0; w < 8; w++) tt += red[w];
        g_hmean[dim] = tt * (1.0f / NN);
    }
}

// --------------------------------------------------------------------------
// Kernel 5: dense flash-GAT on mma.sync (HMMA m16n8k16).
// grid (32, 4), 512 threads (16 warps). warp = (i_quarter, head): 32 i-rows.
// --------------------------------------------------------------------------
#define HTP   136
#define SMO_SIAB 0                    // [4][128] float4 = 8192
#define SMO_EFS  8192                 // [4][128] float4 = 8192
#define SMO_MASK 16384                // [128][HTP] half  = 34816
#define SMO_HT   51200                // [256][HTP] half  = 69632
#define SM_TOT   120832

__device__ __forceinline__ float pcalc(const float4& sab, const float4& efs) {
    float s = sab.x + efs.x;
    return (s >= 0.f) ? sab.y * efs.y : sab.z * efs.z;
}

__global__ __launch_bounds__(512, 1) void attn_kernel(const int* __restrict__ mask) {
    extern __shared__ __align__(16) char sm[];
    float4* siab   = (float4*)(sm + SMO_SIAB);
    float4* efs    = (float4*)(sm + SMO_EFS);
    __half* mask_s = (__half*)(sm + SMO_MASK);
    __half* ht_s   = (__half*)(sm + SMO_HT);

    const int t    = threadIdx.x;
    const int lane = t & 31;
    const int warp = t >> 5;            // 0..15
    const int head = warp & 3;
    const int iq   = warp >> 2;         // 0..3 -> 32 rows each
    const int g    = lane >> 2;
    const int qc   = lane & 3;
    const int i0 = blockIdx.x * MT;
    const int ks = blockIdx.y;

    for (int idx = t; idx < 512; idx += 512) {
        int h = idx >> 7, i = idx & 127;
        float si = g_si[(size_t)(i0 + i) * 4 + h];
        float v = si + g_mx[h];
        float mm = fmaxf(v, 0.2f * v);
        siab[idx] = make_float4(si, __expf(v - mm), __expf(0.2f * v - mm), 0.f);
    }

    float acc[2][8][4];
#pragma unroll
    for (int a = 0; a < 2; a++)
#pragma unroll
        for (int b = 0; b < 8; b++)
#pragma unroll
            for (int d = 0; d < 4; d++) acc[a][b][d] = 0.f;
    float psum[2][2] = {{0.f, 0.f}, {0.f, 0.f}};

    const int4* m4 = (const int4*)mask;

    for (int c = 0; c < NCH; c++) {
        const int j0 = ks * (NN / KSPL) + c * JC;
        __syncthreads();
        // ---- stage hT tile [256 dims][128 j] ----
        for (int idx = t; idx < 4096; idx += 512) {
            int r = idx >> 4, q = idx & 15;
            uint4 v = *(const uint4*)(g_hT + (size_t)r * NN + j0 + q * 8);
            *(uint4*)(ht_s + r * HTP + q * 8) = v;
        }
        // ---- stage mask -> f16 0/1 ----
        for (int idx = t; idx < 4096; idx += 512) {
            int i = idx >> 5, w = idx & 31;
            int4 v = m4[(size_t)(i0 + i) * (NN / 4) + (j0 >> 2) + w];
            uint32_t lo = (v.x ? 0x3C00u : 0u) | (v.y ? 0x3C000000u : 0u);
            uint32_t hi = (v.z ? 0x3C00u : 0u) | (v.w ? 0x3C000000u : 0u);
            *(uint2*)(mask_s + i * HTP + w * 4) = make_uint2(lo, hi);
        }
        // ---- stage efs ----
        for (int idx = t; idx < 512; idx += 512) {
            int h = idx >> 7, j = idx & 127;
            efs[h * 128 + j] = g_efs[(size_t)h * NN + j0 + j];
        }
        __syncthreads();

#pragma unroll 1
        for (int k2 = 0; k2 < JC / 16; k2++) {
            const int jk = k2 * 16;
            uint32_t b0[8], b1[8];
#pragma unroll
            for (int nt = 0; nt < 8; nt++) {
                int dim = head * 64 + nt * 8 + g;
                const __half* bp = ht_s + dim * HTP + jk + qc * 2;
                b0[nt] = *(const uint32_t*)bp;
                b1[nt] = *(const uint32_t*)(bp + 8);
            }
#pragma unroll
            for (int isub = 0; isub < 2; isub++) {
                const int r0 = iq * 32 + isub * 16 + g;
                const int r1 = r0 + 8;
                float4 s0 = siab[head * 128 + r0];
                float4 s1 = siab[head * 128 + r1];
                const int cb = jk + qc * 2;
                float4 e0 = efs[head * 128 + cb];
                float4 e1 = efs[head * 128 + cb + 1];
                float4 e8 = efs[head * 128 + cb + 8];
                float4 e9 = efs[head * 128 + cb + 9];
                float2 m0a = __half22float2(*(__half2*)(mask_s + r0 * HTP + cb));
                float2 m0b = __half22float2(*(__half2*)(mask_s + r0 * HTP + cb + 8));
                float2 m1a = __half22float2(*(__half2*)(mask_s + r1 * HTP + cb));
                float2 m1b = __half22float2(*(__half2*)(mask_s + r1 * HTP + cb + 8));
                float p00 = pcalc(s0, e0) * m0a.x, p01 = pcalc(s0, e1) * m0a.y;
                float p08 = pcalc(s0, e8) * m0b.x, p09 = pcalc(s0, e9) * m0b.y;
                float p10 = pcalc(s1, e0) * m1a.x, p11 = pcalc(s1, e1) * m1a.y;
                float p18 = pcalc(s1, e8) * m1b.x, p19 = pcalc(s1, e9) * m1b.y;
                psum[isub][0] += p00 + p01 + p08 + p09;
                psum[isub][1] += p10 + p11 + p18 + p19;
                __half2 ha0 = __floats2half2_rn(p00, p01);
                __half2 ha1 = __floats2half2_rn(p10, p11);
                __half2 ha2 = __floats2half2_rn(p08, p09);
                __half2 ha3 = __floats2half2_rn(p18, p19);
                uint32_t a0 = *(uint32_t*)&ha0, a1 = *(uint32_t*)&ha1;
                uint32_t a2 = *(uint32_t*)&ha2, a3 = *(uint32_t*)&ha3;
#pragma unroll
                for (int nt = 0; nt < 8; nt++) {
                    asm volatile(
                        "mma.sync.aligned.m16n8k16.row.col.f32.f16.f16.f32 "
                        "{%0,%1,%2,%3}, {%4,%5,%6,%7}, {%8,%9}, {%0,%1,%2,%3};"
                        : "+f"(acc[isub][nt][0]), "+f"(acc[isub][nt][1]),
                          "+f"(acc[isub][nt][2]), "+f"(acc[isub][nt][3])
                        : "r"(a0), "r"(a1), "r"(a2), "r"(a3), "r"(b0[nt]), "r"(b1[nt]));
                }
            }
        }
    }

    // ---- epilogue: store partials + row sums ----
#pragma unroll
    for (int isub = 0; isub < 2; isub++) {
        int ir0 = i0 + iq * 32 + isub * 16 + g;
        int ir1 = ir0 + 8;
        float* d0 = g_part + ((size_t)ks * NN + ir0) * PCOLS;
        float* d1 = g_part + ((size_t)ks * NN + ir1) * PCOLS;
#pragma unroll
        for (int nt = 0; nt < 8; nt++) {
            int dd = head * 64 + nt * 8 + qc * 2;
            *(float2*)(d0 + dd) = make_float2(acc[isub][nt][0], acc[isub][nt][1]);
            *(float2*)(d1 + dd) = make_float2(acc[isub][nt][2], acc[isub][nt][3]);
        }
        float s0 = psum[isub][0], s1 = psum[isub][1];
        s0 += __shfl_xor_sync(0xffffffffu, s0, 1);
        s0 += __shfl_xor_sync(0xffffffffu, s0, 2);
        s1 += __shfl_xor_sync(0xffffffffu, s1, 1);
        s1 += __shfl_xor_sync(0xffffffffu, s1, 2);
        if (qc == 0) {
            d0[256 + head] = s0;
            d1[256 + head] = s1;
        }
    }
}

// --------------------------------------------------------------------------
// Kernel 6: split-K merge + normalize (+ degree-0 fallback).
// --------------------------------------------------------------------------
__global__ __launch_bounds__(256) void merge_kernel(float* __restrict__ out) {
    __shared__ float ss[HEADS];
    const int i = blockIdx.x, t = threadIdx.x;
    const float* p = g_part + (size_t)i * PCOLS;
    const size_t st = (size_t)NN * PCOLS;
    if (t < HEADS)
        ss[t] = p[256 + t] + p[st + 256 + t] + p[2 * st + 256 + t] + p[3 * st + 256 + t];
    __syncthreads();
    float v = p[t] + p[st + t] + p[2 * st + t] + p[3 * st + t];
    float s = ss[t >> 6];
    out[(size_t)i * HD + t] = (s > 0.f) ? v / s : g_hmean[t];
}

// --------------------------------------------------------------------------
extern "C" void kernel_launch(void* const* d_in, const int* in_sizes, int n_in,
                              void* d_out, int out_size) {
    const float* x     = (const float*)d_in[0];
    const int*   mask  = (const int*)d_in[1];
    const float* W     = (const float*)d_in[2];
    const float* a_src = (const float*)d_in[3];
    const float* a_dst = (const float*)d_in[4];
    float*       out   = (float*)d_out;

    cudaFuncSetAttribute(attn_kernel, cudaFuncAttributeMaxDynamicSharedMemorySize, SM_TOT);

    gemm_h_kernel<<<NN / 16, 256>>>(x, W, a_src, a_dst);
    max_sj_kernel<<<1, 256>>>();
    ef_kernel<<<NN / 256, 256>>>();
    hmean_kernel<<<HD, 256>>>();
    attn_kernel<<<dim3(NN / MT, KSPL), 512, SM_TOT>>>(mask);
    merge_kernel<<<NN, 256>>>(out);
}

// round 17
// speedup vs baseline: 1.3443x; 1.1765x over previous
#include <cuda_runtime.h>
#include <cuda_fp16.h>
#include <math.h>
#include <stdint.h>

#define NN      4096
#define IN_DIM  128
#define HEADS   4
#define OUT_DIM 64
#define HD      256
#define MT      128
#define KSPL    4
#define JC      128
#define NCH     (NN / KSPL / JC)    // 8 chunks per block
#define PCOLS   264

// ---- persistent scratch ----
__device__ __half    g_hT[HD * NN];          // h fp16 transposed [dim][j]
__device__ float     g_si[NN * HEADS];
__device__ float     g_sj[NN * HEADS];
__device__ float     g_mx[HEADS];
__device__ uint32_t  g_cS[HEADS * NN / 2];   // half2 (sj[2k], sj[2k+1])
__device__ uint32_t  g_cE[HEADS * NN / 2];   // half2 E pairs
__device__ uint32_t  g_cF[HEADS * NN / 2];   // half2 F pairs
__device__ float     g_part[(size_t)KSPL * NN * PCOLS];

// --------------------------------------------------------------------------
// Kernel 1: h = x @ W -> g_hT (fp16 transposed, smem-transposed stores)
//           + fused per-(node,head) scores.
// --------------------------------------------------------------------------
__global__ __launch_bounds__(256) void gemm_h_kernel(const float* __restrict__ x,
                                                     const float* __restrict__ W,
                                                     const float* __restrict__ a_src,
                                                     const float* __restrict__ a_dst) {
    __shared__ float  xs[16][IN_DIM];
    __shared__ __half hs[16][HD + 8];
    __shared__ float  s_si[16][HEADS];
    __shared__ float  s_sj[16][HEADS];
    const int t = threadIdx.x;
    const int row0 = blockIdx.x * 16;

    for (int idx = t; idx < 16 * IN_DIM; idx += 256)
        xs[idx >> 7][idx & 127] = x[row0 * IN_DIM + idx];
    if (t < 64) { s_si[t >> 2][t & 3] = 0.f; s_sj[t >> 2][t & 3] = 0.f; }
    __syncthreads();

    const int slot = t & 63;
    const int grp  = t >> 6;
    float4 acc[4];
#pragma unroll
    for (int r = 0; r < 4; r++) acc[r] = make_float4(0.f, 0.f, 0.f, 0.f);

    const float4* W4 = (const float4*)W;
#pragma unroll
    for (int kc = 0; kc < IN_DIM; kc += 8) {
        float4 wv[8];
#pragma unroll
        for (int u = 0; u < 8; u++) wv[u] = W4[(kc + u) * 64 + slot];
#pragma unroll
        for (int u = 0; u < 8; u++) {
#pragma unroll
            for (int r = 0; r < 4; r++) {
                float xv = xs[grp * 4 + r][kc + u];
                acc[r].x = fmaf(xv, wv[u].x, acc[r].x);
                acc[r].y = fmaf(xv, wv[u].y, acc[r].y);
                acc[r].z = fmaf(xv, wv[u].z, acc[r].z);
                acc[r].w = fmaf(xv, wv[u].w, acc[r].w);
            }
        }
    }
    // stash h tile in smem for the transpose
#pragma unroll
    for (int r = 0; r < 4; r++) {
        int row = grp * 4 + r;
        *(__half2*)&hs[row][slot * 4]     = __floats2half2_rn(acc[r].x, acc[r].y);
        *(__half2*)&hs[row][slot * 4 + 2] = __floats2half2_rn(acc[r].z, acc[r].w);
    }

    const int d0 = (slot * 4) & 63;
    const int hh = slot >> 4;
    float as0 = a_src[d0], as1 = a_src[d0 + 1], as2 = a_src[d0 + 2], as3 = a_src[d0 + 3];
    float ad0 = a_dst[d0], ad1 = a_dst[d0 + 1], ad2 = a_dst[d0 + 2], ad3 = a_dst[d0 + 3];
#pragma unroll
    for (int r = 0; r < 4; r++) {
        float psi = acc[r].x * as0 + acc[r].y * as1 + acc[r].z * as2 + acc[r].w * as3;
        float psj = acc[r].x * ad0 + acc[r].y * ad1 + acc[r].z * ad2 + acc[r].w * ad3;
        atomicAdd(&s_si[grp * 4 + r][hh], psi);
        atomicAdd(&s_sj[grp * 4 + r][hh], psj);
    }
    __syncthreads();
    // transposed store: thread t = dim, 16 j per store pair (32B)
    {
        uint32_t w[8];
#pragma unroll
        for (int k = 0; k < 8; k++) {
            __half2 h2 = __halves2half2(hs[2 * k][t], hs[2 * k + 1][t]);
            w[k] = *(uint32_t*)&h2;
        }
        *(uint4*)(g_hT + (size_t)t * NN + row0)     = make_uint4(w[0], w[1], w[2], w[3]);
        *(uint4*)(g_hT + (size_t)t * NN + row0 + 8) = make_uint4(w[4], w[5], w[6], w[7]);
    }
    if (t < 64) {
        g_si[(row0 + (t >> 2)) * HEADS + (t & 3)] = s_si[t >> 2][t & 3];
        g_sj[(row0 + (t >> 2)) * HEADS + (t & 3)] = s_sj[t >> 2][t & 3];
    }
}

// --------------------------------------------------------------------------
// Kernel 2: g_mx[h] = max_n sj.
// --------------------------------------------------------------------------
__global__ __launch_bounds__(256) void max_sj_kernel() {
    __shared__ float red[HEADS][8];
    const int t = threadIdx.x, lane = t & 31, wid = t >> 5;
    float mx[HEADS];
#pragma unroll
    for (int h = 0; h < HEADS; h++) mx[h] = -INFINITY;
    const float4* s4 = (const float4*)g_sj;
    for (int i = t; i < NN; i += 256) {
        float4 v = s4[i];
        mx[0] = fmaxf(mx[0], v.x); mx[1] = fmaxf(mx[1], v.y);
        mx[2] = fmaxf(mx[2], v.z); mx[3] = fmaxf(mx[3], v.w);
    }
#pragma unroll
    for (int h = 0; h < HEADS; h++)
#pragma unroll
        for (int d = 16; d; d >>= 1)
            mx[h] = fmaxf(mx[h], __shfl_xor_sync(0xffffffffu, mx[h], d));
    if (lane == 0)
#pragma unroll
        for (int h = 0; h < HEADS; h++) red[h][wid] = mx[h];
    __syncthreads();
    if (t < HEADS) {
        float m = red[t][0];
#pragma unroll
        for (int w = 1; w < 8; w++) m = fmaxf(m, red[t][w]);
        g_mx[t] = m;
    }
}

// --------------------------------------------------------------------------
// Kernel 3: packed half2 factor tables (per j-pair): sj, E, F.
// --------------------------------------------------------------------------
__global__ __launch_bounds__(256) void ef_kernel() {
    int j2 = blockIdx.x * 256 + threadIdx.x;
    if (j2 >= NN / 2) return;
    float4 s0 = ((const float4*)g_sj)[2 * j2];
    float4 s1 = ((const float4*)g_sj)[2 * j2 + 1];
    float a0[4] = {s0.x, s0.y, s0.z, s0.w};
    float a1[4] = {s1.x, s1.y, s1.z, s1.w};
#pragma unroll
    for (int h = 0; h < HEADS; h++) {
        float mxh = g_mx[h];
        float d0 = a0[h] - mxh, d1 = a1[h] - mxh;
        __half2 hS = __floats2half2_rn(a0[h], a1[h]);
        __half2 hE = __floats2half2_rn(__expf(d0), __expf(d1));
        __half2 hF = __floats2half2_rn(__expf(0.2f * d0), __expf(0.2f * d1));
        g_cS[h * (NN / 2) + j2] = *(uint32_t*)&hS;
        g_cE[h * (NN / 2) + j2] = *(uint32_t*)&hE;
        g_cF[h * (NN / 2) + j2] = *(uint32_t*)&hF;
    }
}

// --------------------------------------------------------------------------
// Kernel 4: dense flash-GAT on mma.sync, half2 P-build, sum-via-MMA.
// grid (32, 4), 512 threads (16 warps). warp = (i_quarter, head).
// --------------------------------------------------------------------------
#define HTP   136
#define SMO_SA   0                         // [4][128] u32 = 2048
#define SMO_SB   2048
#define SMO_SS   4096
#define SMO_CE   6144                      // [4][64] u32 = 1024
#define SMO_CF   7168
#define SMO_CS   8192
#define SMO_MASK 9216                      // [128][HTP] half = 34816
#define SMO_HT   44032                     // [256][HTP] half = 69632
#define SM_TOT   113664

__global__ __launch_bounds__(512, 1) void attn_kernel(const int* __restrict__ mask) {
    extern __shared__ __align__(16) char sm[];
    uint32_t* sa_s = (uint32_t*)(sm + SMO_SA);
    uint32_t* sb_s = (uint32_t*)(sm + SMO_SB);
    uint32_t* ss_s = (uint32_t*)(sm + SMO_SS);
    uint32_t* ce_s = (uint32_t*)(sm + SMO_CE);
    uint32_t* cf_s = (uint32_t*)(sm + SMO_CF);
    uint32_t* cs_s = (uint32_t*)(sm + SMO_CS);
    __half*   mask_s = (__half*)(sm + SMO_MASK);
    __half*   ht_s   = (__half*)(sm + SMO_HT);

    const int t    = threadIdx.x;
    const int lane = t & 31;
    const int warp = t >> 5;
    const int head = warp & 3;
    const int iq   = warp >> 2;
    const int g    = lane >> 2;
    const int qc   = lane & 3;
    const int i0 = blockIdx.x * MT;
    const int ks = blockIdx.y;

    // per-row factors: broadcast half2 (A,A), (B,B), (si,si)
    if (t < 512) {
        int h = t >> 7, i = t & 127;
        float si = g_si[(size_t)(i0 + i) * 4 + h];
        float v = si + g_mx[h];
        float mm = fmaxf(v, 0.2f * v);
        __half2 hA = __half2half2(__float2half(__expf(v - mm)));
        __half2 hB = __half2half2(__float2half(__expf(0.2f * v - mm)));
        __half2 hS = __half2half2(__float2half(si));
        sa_s[t] = *(uint32_t*)&hA;
        sb_s[t] = *(uint32_t*)&hB;
        ss_s[t] = *(uint32_t*)&hS;
    }

    float acc[2][8][4];
#pragma unroll
    for (int a = 0; a < 2; a++)
#pragma unroll
        for (int b = 0; b < 8; b++)
#pragma unroll
            for (int d = 0; d < 4; d++) acc[a][b][d] = 0.f;
    float accS[2][4];
#pragma unroll
    for (int a = 0; a < 2; a++)
#pragma unroll
        for (int d = 0; d < 4; d++) accS[a][d] = 0.f;

    const int4* m4 = (const int4*)mask;
    const uint32_t ONES2 = 0x3C003C00u;
    const __half2 zero2 = __float2half2_rn(0.f);

    for (int c = 0; c < NCH; c++) {
        const int j0 = ks * (NN / KSPL) + c * JC;
        __syncthreads();
        // ---- stage hT tile [256 dims][128 j] ----
        for (int idx = t; idx < 4096; idx += 512) {
            int r = idx >> 4, q = idx & 15;
            uint4 v = *(const uint4*)(g_hT + (size_t)r * NN + j0 + q * 8);
            *(uint4*)(ht_s + r * HTP + q * 8) = v;
        }
        // ---- stage mask -> f16 0/1 ----
        for (int idx = t; idx < 4096; idx += 512) {
            int i = idx >> 5, w = idx & 31;
            int4 v = m4[(size_t)(i0 + i) * (NN / 4) + (j0 >> 2) + w];
            uint32_t lo = (v.x ? 0x3C00u : 0u) | (v.y ? 0x3C000000u : 0u);
            uint32_t hi = (v.z ? 0x3C00u : 0u) | (v.w ? 0x3C000000u : 0u);
            *(uint2*)(mask_s + i * HTP + w * 4) = make_uint2(lo, hi);
        }
        // ---- stage packed factor tables ----
        if (t < 256) {
            int h = t >> 6, j2 = t & 63;
            int src = h * (NN / 2) + (j0 >> 1) + j2;
            ce_s[h * 64 + j2] = g_cE[src];
            cf_s[h * 64 + j2] = g_cF[src];
            cs_s[h * 64 + j2] = g_cS[src];
        }
        __syncthreads();

#pragma unroll 1
        for (int k2 = 0; k2 < JC / 16; k2++) {
            const int jk = k2 * 16;
            const int cb = jk + qc * 2;
            const int cbh = (jk >> 1) + qc;
            // ---- B fragments ----
            uint32_t b0[8], b1[8];
#pragma unroll
            for (int nt = 0; nt < 8; nt++) {
                int dim = head * 64 + nt * 8 + g;
                const __half* bp = ht_s + dim * HTP + cb;
                b0[nt] = *(const uint32_t*)bp;
                b1[nt] = *(const uint32_t*)(bp + 8);
            }
            // ---- hoisted column factors ----
            __half2 sj_a = *(__half2*)&cs_s[head * 64 + cbh];
            __half2 sj_b = *(__half2*)&cs_s[head * 64 + cbh + 4];
            __half2 E_a  = *(__half2*)&ce_s[head * 64 + cbh];
            __half2 E_b  = *(__half2*)&ce_s[head * 64 + cbh + 4];
            __half2 F_a  = *(__half2*)&cf_s[head * 64 + cbh];
            __half2 F_b  = *(__half2*)&cf_s[head * 64 + cbh + 4];

#pragma unroll
            for (int isub = 0; isub < 2; isub++) {
                const int r0 = iq * 32 + isub * 16 + g;
                const int r1 = r0 + 8;
                __half2 si0 = *(__half2*)&ss_s[head * 128 + r0];
                __half2 A0  = *(__half2*)&sa_s[head * 128 + r0];
                __half2 B0  = *(__half2*)&sb_s[head * 128 + r0];
                __half2 si1 = *(__half2*)&ss_s[head * 128 + r1];
                __half2 A1  = *(__half2*)&sa_s[head * 128 + r1];
                __half2 B1  = *(__half2*)&sb_s[head * 128 + r1];

                __half2 m0a = *(__half2*)(mask_s + r0 * HTP + cb);
                __half2 m0b = *(__half2*)(mask_s + r0 * HTP + cb + 8);
                __half2 m1a = *(__half2*)(mask_s + r1 * HTP + cb);
                __half2 m1b = *(__half2*)(mask_s + r1 * HTP + cb + 8);

                // p = (s>=0 ? A*E : B*F) * mask, all half2
                __half2 c0a = __hge2(__hadd2(si0, sj_a), zero2);
                __half2 c0b = __hge2(__hadd2(si0, sj_b), zero2);
                __half2 c1a = __hge2(__hadd2(si1, sj_a), zero2);
                __half2 c1b = __hge2(__hadd2(si1, sj_b), zero2);
                __half2 AE0a = __hmul2(A0, E_a), BF0a = __hmul2(B0, F_a);
                __half2 AE0b = __hmul2(A0, E_b), BF0b = __hmul2(B0, F_b);
                __half2 AE1a = __hmul2(A1, E_a), BF1a = __hmul2(B1, F_a);
                __half2 AE1b = __hmul2(A1, E_b), BF1b = __hmul2(B1, F_b);
                __half2 p0a = __hmul2(__hfma2(c0a, __hsub2(AE0a, BF0a), BF0a), m0a);
                __half2 p0b = __hmul2(__hfma2(c0b, __hsub2(AE0b, BF0b), BF0b), m0b);
                __half2 p1a = __hmul2(__hfma2(c1a, __hsub2(AE1a, BF1a), BF1a), m1a);
                __half2 p1b = __hmul2(__hfma2(c1b, __hsub2(AE1b, BF1b), BF1b), m1b);

                uint32_t a0 = *(uint32_t*)&p0a, a1 = *(uint32_t*)&p1a;
                uint32_t a2 = *(uint32_t*)&p0b, a3 = *(uint32_t*)&p1b;
#pragma unroll
                for (int nt = 0; nt < 8; nt++) {
                    asm volatile(
                        "mma.sync.aligned.m16n8k16.row.col.f32.f16.f16.f32 "
                        "{%0,%1,%2,%3}, {%4,%5,%6,%7}, {%8,%9}, {%0,%1,%2,%3};"
                        : "+f"(acc[isub][nt][0]), "+f"(acc[isub][nt][1]),
                          "+f"(acc[isub][nt][2]), "+f"(acc[isub][nt][3])
                        : "r"(a0), "r"(a1), "r"(a2), "r"(a3), "r"(b0[nt]), "r"(b1[nt]));
                }
                // row-sum MMA with ones-B
                asm volatile(
                    "mma.sync.aligned.m16n8k16.row.col.f32.f16.f16.f32 "
                    "{%0,%1,%2,%3}, {%4,%5,%6,%7}, {%8,%9}, {%0,%1,%2,%3};"
                    : "+f"(accS[isub][0]), "+f"(accS[isub][1]),
                      "+f"(accS[isub][2]), "+f"(accS[isub][3])
                    : "r"(a0), "r"(a1), "r"(a2), "r"(a3), "r"(ONES2), "r"(ONES2));
            }
        }
    }

    // ---- epilogue: partials + row sums (no shuffles needed) ----
#pragma unroll
    for (int isub = 0; isub < 2; isub++) {
        int ir0 = i0 + iq * 32 + isub * 16 + g;
        int ir1 = ir0 + 8;
        float* d0 = g_part + ((size_t)ks * NN + ir0) * PCOLS;
        float* d1 = g_part + ((size_t)ks * NN + ir1) * PCOLS;
#pragma unroll
        for (int nt = 0; nt < 8; nt++) {
            int dd = head * 64 + nt * 8 + qc * 2;
            *(float2*)(d0 + dd) = make_float2(acc[isub][nt][0], acc[isub][nt][1]);
            *(float2*)(d1 + dd) = make_float2(acc[isub][nt][2], acc[isub][nt][3]);
        }
        if (qc == 0) {
            d0[256 + head] = accS[isub][0];
            d1[256 + head] = accS[isub][2];
        }
    }
}

// --------------------------------------------------------------------------
// Kernel 5: split-K merge + normalize (lazy degree-0 fallback).
// --------------------------------------------------------------------------
__global__ __launch_bounds__(256) void merge_kernel(float* __restrict__ out) {
    __shared__ float ss[HEADS];
    const int i = blockIdx.x, t = threadIdx.x;
    const float* p = g_part + (size_t)i * PCOLS;
    const size_t st = (size_t)NN * PCOLS;
    if (t < HEADS)
        ss[t] = p[256 + t] + p[st + 256 + t] + p[2 * st + 256 + t] + p[3 * st + 256 + t];
    __syncthreads();
    float v = p[t] + p[st + t] + p[2 * st + t] + p[3 * st + t];
    float s = ss[t >> 6];
    float r;
    if (s > 0.f) {
        r = v / s;
    } else {
        // degree-0 row (prob ~0): exact uniform mean of h column t
        const __half2* hp = (const __half2*)(g_hT + (size_t)t * NN);
        float m = 0.f;
        for (int j = 0; j < NN / 2; j++) {
            float2 f = __half22float2(hp[j]);
            m += f.x + f.y;
        }
        r = m * (1.0f / NN);
    }
    out[(size_t)i * HD + t] = r;
}

// --------------------------------------------------------------------------
extern "C" void kernel_launch(void* const* d_in, const int* in_sizes, int n_in,
                              void* d_out, int out_size) {
    const float* x     = (const float*)d_in[0];
    const int*   mask  = (const int*)d_in[1];
    const float* W     = (const float*)d_in[2];
    const float* a_src = (const float*)d_in[3];
    const float* a_dst = (const float*)d_in[4];
    float*       out   = (float*)d_out;

    cudaFuncSetAttribute(attn_kernel, cudaFuncAttributeMaxDynamicSharedMemorySize, SM_TOT);

    gemm_h_kernel<<<NN / 16, 256>>>(x, W, a_src, a_dst);
    max_sj_kernel<<<1, 256>>>();
    ef_kernel<<<NN / 512, 256>>>();
    attn_kernel<<<dim3(NN / MT, KSPL), 512, SM_TOT>>>(mask);
    merge_kernel<<<NN, 256>>>(out);
}